// round 1
// baseline (speedup 1.0000x reference)
#include <cuda_runtime.h>
#include <cuda_bf16.h>
#include <cstdint>
#include <math.h>

#define B_SZ   1024
#define RANK   256
#define NENT   100000
#define NREL   1000
#define MAXNB  50

#define BM 128
#define BN 128
#define BK 32
#define KPAD 36

// scratch (allocation-free rule: device globals)
__device__ __align__(16) float g_q[B_SZ * RANK];       // gated query vectors, 1 MB
__device__ __align__(16) float g_Wt[512 * 256];        // W_w transposed  [i][j] = W_w[j][i]
__device__ __align__(16) float g_W2t[256 * 256];       // W2_w transposed [k][j] = W2_w[j][k]

__device__ __forceinline__ float to_tf32(float x) {
    uint32_t u;
    asm("cvt.rna.tf32.f32 %0, %1;" : "=r"(u) : "f"(x));
    return __uint_as_float(u);
}

__device__ __forceinline__ void mma_tf32(float* c, const uint32_t* a, uint32_t b0, uint32_t b1) {
    asm volatile(
        "mma.sync.aligned.m16n8k8.row.col.f32.tf32.tf32.f32 "
        "{%0,%1,%2,%3}, {%4,%5,%6,%7}, {%8,%9}, {%0,%1,%2,%3};\n"
        : "+f"(c[0]), "+f"(c[1]), "+f"(c[2]), "+f"(c[3])
        : "r"(a[0]), "r"(a[1]), "r"(a[2]), "r"(a[3]), "r"(b0), "r"(b1));
}

// ---------------------------------------------------------------------------
// Kernel 0: transpose W_w (256x512 -> 512x256) and W2_w (256x256 -> 256x256)
// so the per-row matvecs in prep read coalesced columns.
// ---------------------------------------------------------------------------
__global__ void transpose_kernel(const float* __restrict__ W_w,
                                 const float* __restrict__ W2_w) {
    int idx = blockIdx.x * blockDim.x + threadIdx.x;
    if (idx < 512 * 256) {
        int i = idx >> 8, j = idx & 255;          // Wt[i][j] = W_w[j][i]
        g_Wt[idx] = W_w[j * 512 + i];
    } else {
        int idx2 = idx - 512 * 256;
        if (idx2 < 256 * 256) {
            int k = idx2 >> 8, j = idx2 & 255;    // W2t[k][j] = W2_w[j][k]
            g_W2t[idx2] = W2_w[j * 256 + k];
        }
    }
}

// ---------------------------------------------------------------------------
// Kernel 1: prep — gathers, attention, gating. One block per 8 batch rows.
// 256 threads; thread t owns feature dim k=t.
// ---------------------------------------------------------------------------
__global__ __launch_bounds__(256) void prep_kernel(
    const int* __restrict__ x, const int* __restrict__ nb_idx,
    const float* __restrict__ lhs_w, const float* __restrict__ rel_w,
    const float* __restrict__ rhs_w,
    const float* __restrict__ W_b, const float* __restrict__ W2_b,
    const float* __restrict__ Wo_w, const float* __restrict__ Wo_b,
    const float* __restrict__ Uo_w, const float* __restrict__ Uo_b,
    float* __restrict__ aux)                     // lhs|rel|rhs|e_c, or null
{
    __shared__ float trp[8][512];
    __shared__ float w_sm[8][256];
    __shared__ float alpha[8][64];
    __shared__ float ctx_sm[8][256];
    __shared__ float red[8][8];
    __shared__ float g_sm[8];

    const int t = threadIdx.x;
    const int b0 = blockIdx.x * 8;
    const int lane = t & 31;
    const int warp = t >> 5;

    float lhsrel[8];
#pragma unroll
    for (int bb = 0; bb < 8; bb++) {
        int b = b0 + bb;
        int i0 = x[b * 3 + 0];
        int i1 = x[b * 3 + 1];
        int i2 = x[b * 3 + 2];
        float lv = lhs_w[(size_t)i0 * RANK + t];
        float rv = rel_w[(size_t)i1 * RANK + t];
        float hv = rhs_w[(size_t)i2 * RANK + t];
        trp[bb][t]       = lv;
        trp[bb][256 + t] = rv;
        lhsrel[bb] = lv * rv;
        if (aux) {
            aux[(size_t)b * RANK + t]              = lv;   // lhs
            aux[262144 + (size_t)b * RANK + t]     = rv;   // rel
            aux[2 * 262144 + (size_t)b * RANK + t] = hv;   // rhs
        }
    }
    __syncthreads();

    // w[b][t] = sum_i W_w[t][i] * trp[b][i] + W_b[t]   (coalesced via g_Wt)
    {
        float acc[8];
#pragma unroll
        for (int bb = 0; bb < 8; bb++) acc[bb] = 0.f;
        for (int i = 0; i < 512; i += 4) {
            float wv0 = g_Wt[(i + 0) * 256 + t];
            float wv1 = g_Wt[(i + 1) * 256 + t];
            float wv2 = g_Wt[(i + 2) * 256 + t];
            float wv3 = g_Wt[(i + 3) * 256 + t];
#pragma unroll
            for (int bb = 0; bb < 8; bb++) {
                const float4 tv = *reinterpret_cast<const float4*>(&trp[bb][i]);
                acc[bb] += wv0 * tv.x + wv1 * tv.y + wv2 * tv.z + wv3 * tv.w;
            }
        }
        float bias = W_b[t];
#pragma unroll
        for (int bb = 0; bb < 8; bb++) w_sm[bb][t] = acc[bb] + bias;
    }
    __syncthreads();

    // attention scores + softmax: warp wg handles batch row bb = wg
    {
        int bb = warp;
        int b = b0 + bb;
        for (int m = 0; m < MAXNB; m++) {
            int nb = __ldg(&nb_idx[b * MAXNB + m]);
            const float* r = rhs_w + (size_t)nb * RANK;
            float s = 0.f;
#pragma unroll
            for (int j = 0; j < 8; j++) {
                int k = lane + 32 * j;
                s += w_sm[bb][k] * __ldg(&r[k]);
            }
#pragma unroll
            for (int o = 16; o > 0; o >>= 1) s += __shfl_xor_sync(0xffffffffu, s, o);
            if (lane == 0) alpha[bb][m] = s;
        }
        __syncwarp();
        float v1 = (lane < MAXNB) ? alpha[bb][lane] : -1e30f;
        float v2 = (lane + 32 < MAXNB) ? alpha[bb][lane + 32] : -1e30f;
        float mx = fmaxf(v1, v2);
#pragma unroll
        for (int o = 16; o > 0; o >>= 1) mx = fmaxf(mx, __shfl_xor_sync(0xffffffffu, mx, o));
        float e1 = (lane < MAXNB) ? expf(v1 - mx) : 0.f;
        float e2 = (lane + 32 < MAXNB) ? expf(v2 - mx) : 0.f;
        float sm = e1 + e2;
#pragma unroll
        for (int o = 16; o > 0; o >>= 1) sm += __shfl_xor_sync(0xffffffffu, sm, o);
        float inv = 1.f / sm;
        if (lane < MAXNB) alpha[bb][lane] = e1 * inv;
        if (lane + 32 < MAXNB) alpha[bb][lane + 32] = e2 * inv;
    }
    __syncthreads();

    // ctx[b][t] = sum_m alpha[b][m] * rhs_w[nb[b][m]][t]
#pragma unroll
    for (int bb = 0; bb < 8; bb++) {
        int base = (b0 + bb) * MAXNB;
        float acc = 0.f;
        for (int m = 0; m < MAXNB; m++) {
            int nb = __ldg(&nb_idx[base + m]);
            acc += alpha[bb][m] * __ldg(&rhs_w[(size_t)nb * RANK + t]);
        }
        ctx_sm[bb][t] = acc;
    }
    __syncthreads();

    // e_c[b][t] = sum_k W2_w[t][k] * ctx[b][k] + W2_b[t]
    float ec[8];
    {
        float acc[8];
#pragma unroll
        for (int bb = 0; bb < 8; bb++) acc[bb] = 0.f;
        for (int k = 0; k < 256; k += 4) {
            float w0 = g_W2t[(k + 0) * 256 + t];
            float w1 = g_W2t[(k + 1) * 256 + t];
            float w2 = g_W2t[(k + 2) * 256 + t];
            float w3 = g_W2t[(k + 3) * 256 + t];
#pragma unroll
            for (int bb = 0; bb < 8; bb++) {
                const float4 cv = *reinterpret_cast<const float4*>(&ctx_sm[bb][k]);
                acc[bb] += w0 * cv.x + w1 * cv.y + w2 * cv.z + w3 * cv.w;
            }
        }
        float bias = W2_b[t];
#pragma unroll
        for (int bb = 0; bb < 8; bb++) {
            ec[bb] = acc[bb] + bias;
            if (aux) aux[3 * 262144 + (size_t)(b0 + bb) * RANK + t] = ec[bb];
        }
    }

    // gate: g = sigmoid(Uo . (lhs*rel) + Uo_b + Wo . e_c + Wo_b)
    {
        float uo = Uo_w[t], wo = Wo_w[t];
#pragma unroll
        for (int bb = 0; bb < 8; bb++) {
            float c = uo * lhsrel[bb] + wo * ec[bb];
#pragma unroll
            for (int o = 16; o > 0; o >>= 1) c += __shfl_xor_sync(0xffffffffu, c, o);
            if (lane == 0) red[bb][warp] = c;
        }
        __syncthreads();
        if (t < 8) {
            float s = 0.f;
#pragma unroll
            for (int w = 0; w < 8; w++) s += red[t][w];
            s += Uo_b[0] + Wo_b[0];
            g_sm[t] = 1.f / (1.f + expf(-s));
        }
        __syncthreads();
    }

    // q = lhs*rel * (g*e_c + 1 - g)
#pragma unroll
    for (int bb = 0; bb < 8; bb++) {
        float g = g_sm[bb];
        g_q[(size_t)(b0 + bb) * RANK + t] = lhsrel[bb] * (g * ec[bb] + 1.f - g);
    }
}

// ---------------------------------------------------------------------------
// Kernel 2: tot_forward = q (1024x256) @ rhs_w^T (256x100000), TF32 mma.
// 128x128 tiles, BK=32 chunks, single smem stage with register prefetch.
// Grid: x = 8 m-tiles (fast, shares B tile in L2), y = 782 n-tiles.
// ---------------------------------------------------------------------------
__global__ __launch_bounds__(256, 1) void gemm_tf32_kernel(
    const float* __restrict__ rhs_w, float* __restrict__ out)
{
    __shared__ float As[BM * KPAD];
    __shared__ float Bs[BN * KPAD];

    const int tid = threadIdx.x;
    const int m0 = blockIdx.x * BM;
    const int n0 = blockIdx.y * BN;
    const int lane = tid & 31;
    const int warp = tid >> 5;
    const int wm = warp & 3;    // m offset 32*wm
    const int wn = warp >> 2;   // n offset 64*wn
    const int gid = lane >> 2;
    const int qid = lane & 3;

    int ar[4], ac[4];
#pragma unroll
    for (int i = 0; i < 4; i++) {
        int idx = tid + i * 256;
        ar[i] = idx >> 3;
        ac[i] = (idx & 7) * 4;
    }

    float4 ga[4], gb[4];

    auto load_chunk = [&](int kc) {
#pragma unroll
        for (int i = 0; i < 4; i++) {
            ga[i] = *reinterpret_cast<const float4*>(
                g_q + (size_t)(m0 + ar[i]) * 256 + kc + ac[i]);
            int nr = n0 + ar[i];
            if (nr < NENT)
                gb[i] = *reinterpret_cast<const float4*>(
                    rhs_w + (size_t)nr * 256 + kc + ac[i]);
            else
                gb[i] = make_float4(0.f, 0.f, 0.f, 0.f);
        }
    };
    auto store_chunk = [&]() {
#pragma unroll
        for (int i = 0; i < 4; i++) {
            float4 va = make_float4(to_tf32(ga[i].x), to_tf32(ga[i].y),
                                    to_tf32(ga[i].z), to_tf32(ga[i].w));
            float4 vb = make_float4(to_tf32(gb[i].x), to_tf32(gb[i].y),
                                    to_tf32(gb[i].z), to_tf32(gb[i].w));
            *reinterpret_cast<float4*>(&As[ar[i] * KPAD + ac[i]]) = va;
            *reinterpret_cast<float4*>(&Bs[ar[i] * KPAD + ac[i]]) = vb;
        }
    };

    float acc[2][8][4];
#pragma unroll
    for (int tm = 0; tm < 2; tm++)
#pragma unroll
        for (int tn = 0; tn < 8; tn++)
#pragma unroll
            for (int r = 0; r < 4; r++) acc[tm][tn][r] = 0.f;

    load_chunk(0);
    store_chunk();
    __syncthreads();

    const uint32_t* Au = reinterpret_cast<const uint32_t*>(As);
    const uint32_t* Bu = reinterpret_cast<const uint32_t*>(Bs);

#pragma unroll 1
    for (int c = 0; c < 256 / BK; c++) {
        if (c < 256 / BK - 1) load_chunk((c + 1) * BK);

#pragma unroll
        for (int kk = 0; kk < BK; kk += 8) {
            uint32_t af[2][4];
#pragma unroll
            for (int tm = 0; tm < 2; tm++) {
                int r = wm * 32 + tm * 16 + gid;
                af[tm][0] = Au[r * KPAD + kk + qid];
                af[tm][1] = Au[(r + 8) * KPAD + kk + qid];
                af[tm][2] = Au[r * KPAD + kk + qid + 4];
                af[tm][3] = Au[(r + 8) * KPAD + kk + qid + 4];
            }
#pragma unroll
            for (int tn = 0; tn < 8; tn++) {
                int nr = wn * 64 + tn * 8 + gid;
                uint32_t bf0 = Bu[nr * KPAD + kk + qid];
                uint32_t bf1 = Bu[nr * KPAD + kk + qid + 4];
                mma_tf32(acc[0][tn], af[0], bf0, bf1);
                mma_tf32(acc[1][tn], af[1], bf0, bf1);
            }
        }
        __syncthreads();
        if (c < 256 / BK - 1) {
            store_chunk();
            __syncthreads();
        }
    }

    // epilogue
#pragma unroll
    for (int tm = 0; tm < 2; tm++) {
        int r = m0 + wm * 32 + tm * 16 + gid;
#pragma unroll
        for (int tn = 0; tn < 8; tn++) {
            int cb = n0 + wn * 64 + tn * 8 + 2 * qid;
            if (cb < NENT) {
                float2 v0 = make_float2(acc[tm][tn][0], acc[tm][tn][1]);
                float2 v1 = make_float2(acc[tm][tn][2], acc[tm][tn][3]);
                *reinterpret_cast<float2*>(out + (size_t)r * NENT + cb) = v0;
                *reinterpret_cast<float2*>(out + (size_t)(r + 8) * NENT + cb) = v1;
            }
        }
    }
}

// ---------------------------------------------------------------------------
extern "C" void kernel_launch(void* const* d_in, const int* in_sizes, int n_in,
                              void* d_out, int out_size) {
    const int*   x      = (const int*)d_in[0];
    const int*   nb     = (const int*)d_in[1];
    const float* lhs_w  = (const float*)d_in[2];
    const float* rel_w  = (const float*)d_in[3];
    const float* rhs_w  = (const float*)d_in[4];
    const float* W_w    = (const float*)d_in[5];
    const float* W_b    = (const float*)d_in[6];
    const float* W2_w   = (const float*)d_in[7];
    const float* W2_b   = (const float*)d_in[8];
    const float* Wo_w   = (const float*)d_in[9];
    const float* Wo_b   = (const float*)d_in[10];
    const float* Uo_w   = (const float*)d_in[11];
    const float* Uo_b   = (const float*)d_in[12];
    float* out = (float*)d_out;

    float* aux = nullptr;
    if (out_size >= 102400000 + 4 * 262144) aux = out + 102400000;

    transpose_kernel<<<(512 * 256 + 256 * 256 + 255) / 256, 256>>>(W_w, W2_w);
    prep_kernel<<<B_SZ / 8, 256>>>(x, nb, lhs_w, rel_w, rhs_w,
                                   W_b, W2_b, Wo_w, Wo_b, Uo_w, Uo_b, aux);
    dim3 grid(B_SZ / BM, (NENT + BN - 1) / BN);
    gemm_tf32_kernel<<<grid, 256>>>(rhs_w, out);
}

// round 2
// speedup vs baseline: 1.1920x; 1.1920x over previous
#include <cuda_runtime.h>
#include <cuda_bf16.h>
#include <cstdint>
#include <math.h>

#define B_SZ   1024
#define RANK   256
#define NENT   100000
#define NREL   1000
#define MAXNB  50

// GEMM tiling
#define BM 128
#define BN 256
#define BK 32
#define KP 36                      // padded K stride in words (conflict-free)
#define NST 3                      // cp.async pipeline stages
#define A_WORDS (BM * KP)          // 4608
#define B_WORDS (BN * KP)          // 9216
#define STG_WORDS (A_WORDS + B_WORDS)
#define SMEM_BYTES (NST * STG_WORDS * 4)

// scratch (allocation-free rule: device globals)
__device__ __align__(16) float g_q[B_SZ * RANK];       // gated query vectors (tf32-rounded)
__device__ __align__(16) float g_Wt[512 * 256];        // W_w transposed
__device__ __align__(16) float g_W2t[256 * 256];       // W2_w transposed

__device__ __forceinline__ float to_tf32(float x) {
    uint32_t u;
    asm("cvt.rna.tf32.f32 %0, %1;" : "=r"(u) : "f"(x));
    return __uint_as_float(u);
}

__device__ __forceinline__ void mma_tf32(float* c, const uint32_t* a, uint32_t b0, uint32_t b1) {
    asm volatile(
        "mma.sync.aligned.m16n8k8.row.col.f32.tf32.tf32.f32 "
        "{%0,%1,%2,%3}, {%4,%5,%6,%7}, {%8,%9}, {%0,%1,%2,%3};\n"
        : "+f"(c[0]), "+f"(c[1]), "+f"(c[2]), "+f"(c[3])
        : "r"(a[0]), "r"(a[1]), "r"(a[2]), "r"(a[3]), "r"(b0), "r"(b1));
}

__device__ __forceinline__ void cp16(uint32_t saddr, const float* gptr, int sz) {
    asm volatile("cp.async.cg.shared.global [%0], [%1], 16, %2;\n"
                 :: "r"(saddr), "l"(gptr), "r"(sz));
}

// ---------------------------------------------------------------------------
// Kernel 0: transpose W_w (256x512 -> 512x256) and W2_w (256x256)
// ---------------------------------------------------------------------------
__global__ void transpose_kernel(const float* __restrict__ W_w,
                                 const float* __restrict__ W2_w) {
    int idx = blockIdx.x * blockDim.x + threadIdx.x;
    if (idx < 512 * 256) {
        int i = idx >> 8, j = idx & 255;
        g_Wt[idx] = W_w[j * 512 + i];
    } else {
        int idx2 = idx - 512 * 256;
        if (idx2 < 256 * 256) {
            int k = idx2 >> 8, j = idx2 & 255;
            g_W2t[idx2] = W2_w[j * 256 + k];
        }
    }
}

// ---------------------------------------------------------------------------
// Kernel 1: prep — gathers, attention, gating. One block per 8 batch rows.
// ---------------------------------------------------------------------------
__global__ __launch_bounds__(256) void prep_kernel(
    const int* __restrict__ x, const int* __restrict__ nb_idx,
    const float* __restrict__ lhs_w, const float* __restrict__ rel_w,
    const float* __restrict__ rhs_w,
    const float* __restrict__ W_b, const float* __restrict__ W2_b,
    const float* __restrict__ Wo_w, const float* __restrict__ Wo_b,
    const float* __restrict__ Uo_w, const float* __restrict__ Uo_b,
    float* __restrict__ aux)
{
    __shared__ float trp[8][512];
    __shared__ float w_sm[8][256];
    __shared__ float alpha[8][64];
    __shared__ float ctx_sm[8][256];
    __shared__ float red[8][8];
    __shared__ float g_sm[8];

    const int t = threadIdx.x;
    const int b0 = blockIdx.x * 8;
    const int lane = t & 31;
    const int warp = t >> 5;

    float lhsrel[8];
#pragma unroll
    for (int bb = 0; bb < 8; bb++) {
        int b = b0 + bb;
        int i0 = x[b * 3 + 0];
        int i1 = x[b * 3 + 1];
        int i2 = x[b * 3 + 2];
        float lv = lhs_w[(size_t)i0 * RANK + t];
        float rv = rel_w[(size_t)i1 * RANK + t];
        float hv = rhs_w[(size_t)i2 * RANK + t];
        trp[bb][t]       = lv;
        trp[bb][256 + t] = rv;
        lhsrel[bb] = lv * rv;
        if (aux) {
            aux[(size_t)b * RANK + t]              = lv;
            aux[262144 + (size_t)b * RANK + t]     = rv;
            aux[2 * 262144 + (size_t)b * RANK + t] = hv;
        }
    }
    __syncthreads();

    // w = trp_E @ W_w.T + W_b
    {
        float acc[8];
#pragma unroll
        for (int bb = 0; bb < 8; bb++) acc[bb] = 0.f;
        for (int i = 0; i < 512; i += 4) {
            float wv0 = g_Wt[(i + 0) * 256 + t];
            float wv1 = g_Wt[(i + 1) * 256 + t];
            float wv2 = g_Wt[(i + 2) * 256 + t];
            float wv3 = g_Wt[(i + 3) * 256 + t];
#pragma unroll
            for (int bb = 0; bb < 8; bb++) {
                const float4 tv = *reinterpret_cast<const float4*>(&trp[bb][i]);
                acc[bb] += wv0 * tv.x + wv1 * tv.y + wv2 * tv.z + wv3 * tv.w;
            }
        }
        float bias = W_b[t];
#pragma unroll
        for (int bb = 0; bb < 8; bb++) w_sm[bb][t] = acc[bb] + bias;
    }
    __syncthreads();

    // attention + softmax (warp per row)
    {
        int bb = warp;
        int b = b0 + bb;
        for (int m = 0; m < MAXNB; m++) {
            int nb = __ldg(&nb_idx[b * MAXNB + m]);
            const float* r = rhs_w + (size_t)nb * RANK;
            float s = 0.f;
#pragma unroll
            for (int j = 0; j < 8; j++) {
                int k = lane + 32 * j;
                s += w_sm[bb][k] * __ldg(&r[k]);
            }
#pragma unroll
            for (int o = 16; o > 0; o >>= 1) s += __shfl_xor_sync(0xffffffffu, s, o);
            if (lane == 0) alpha[bb][m] = s;
        }
        __syncwarp();
        float v1 = (lane < MAXNB) ? alpha[bb][lane] : -1e30f;
        float v2 = (lane + 32 < MAXNB) ? alpha[bb][lane + 32] : -1e30f;
        float mx = fmaxf(v1, v2);
#pragma unroll
        for (int o = 16; o > 0; o >>= 1) mx = fmaxf(mx, __shfl_xor_sync(0xffffffffu, mx, o));
        float e1 = (lane < MAXNB) ? expf(v1 - mx) : 0.f;
        float e2 = (lane + 32 < MAXNB) ? expf(v2 - mx) : 0.f;
        float sm = e1 + e2;
#pragma unroll
        for (int o = 16; o > 0; o >>= 1) sm += __shfl_xor_sync(0xffffffffu, sm, o);
        float inv = 1.f / sm;
        if (lane < MAXNB) alpha[bb][lane] = e1 * inv;
        if (lane + 32 < MAXNB) alpha[bb][lane + 32] = e2 * inv;
    }
    __syncthreads();

    // ctx = alpha-weighted neighbor sum
#pragma unroll
    for (int bb = 0; bb < 8; bb++) {
        int base = (b0 + bb) * MAXNB;
        float acc = 0.f;
        for (int m = 0; m < MAXNB; m++) {
            int nb = __ldg(&nb_idx[base + m]);
            acc += alpha[bb][m] * __ldg(&rhs_w[(size_t)nb * RANK + t]);
        }
        ctx_sm[bb][t] = acc;
    }
    __syncthreads();

    // e_c = ctx @ W2_w.T + W2_b
    float ec[8];
    {
        float acc[8];
#pragma unroll
        for (int bb = 0; bb < 8; bb++) acc[bb] = 0.f;
        for (int k = 0; k < 256; k += 4) {
            float w0 = g_W2t[(k + 0) * 256 + t];
            float w1 = g_W2t[(k + 1) * 256 + t];
            float w2 = g_W2t[(k + 2) * 256 + t];
            float w3 = g_W2t[(k + 3) * 256 + t];
#pragma unroll
            for (int bb = 0; bb < 8; bb++) {
                const float4 cv = *reinterpret_cast<const float4*>(&ctx_sm[bb][k]);
                acc[bb] += w0 * cv.x + w1 * cv.y + w2 * cv.z + w3 * cv.w;
            }
        }
        float bias = W2_b[t];
#pragma unroll
        for (int bb = 0; bb < 8; bb++) {
            ec[bb] = acc[bb] + bias;
            if (aux) aux[3 * 262144 + (size_t)(b0 + bb) * RANK + t] = ec[bb];
        }
    }

    // gate
    {
        float uo = Uo_w[t], wo = Wo_w[t];
#pragma unroll
        for (int bb = 0; bb < 8; bb++) {
            float c = uo * lhsrel[bb] + wo * ec[bb];
#pragma unroll
            for (int o = 16; o > 0; o >>= 1) c += __shfl_xor_sync(0xffffffffu, c, o);
            if (lane == 0) red[bb][warp] = c;
        }
        __syncthreads();
        if (t < 8) {
            float s = 0.f;
#pragma unroll
            for (int w = 0; w < 8; w++) s += red[t][w];
            s += Uo_b[0] + Wo_b[0];
            g_sm[t] = 1.f / (1.f + expf(-s));
        }
        __syncthreads();
    }

    // q = lhs*rel*(g*e_c + 1 - g), pre-rounded to tf32 (RNA)
#pragma unroll
    for (int bb = 0; bb < 8; bb++) {
        float g = g_sm[bb];
        g_q[(size_t)(b0 + bb) * RANK + t] = to_tf32(lhsrel[bb] * (g * ec[bb] + 1.f - g));
    }
}

// ---------------------------------------------------------------------------
// Kernel 2: tot_forward = q (1024x256) @ rhs_w^T. TF32 mma, 128x256 tiles,
// 3-stage cp.async pipeline, warp tile 64x64, streaming stores.
// ---------------------------------------------------------------------------
__global__ __launch_bounds__(256, 1) void gemm_tf32_kernel(
    const float* __restrict__ rhs_w, float* __restrict__ out)
{
    extern __shared__ float smem[];

    const int tid = threadIdx.x;
    const int m0 = blockIdx.x * BM;
    const int n0 = blockIdx.y * BN;
    const int lane = tid & 31;
    const int warp = tid >> 5;
    const int wm = warp & 1;    // m offset 64*wm
    const int wn = warp >> 1;   // n offset 64*wn
    const int gid = lane >> 2;
    const int qid = lane & 3;

    const uint32_t smem_u32 = (uint32_t)__cvta_generic_to_shared(smem);

    // per-thread load coordinates (row = idx/8, 4-float column = (idx%8)*4)
    auto issue_stage = [&](int buf, int kc) {
        uint32_t base = smem_u32 + (uint32_t)(buf * STG_WORDS) * 4u;
#pragma unroll
        for (int i = 0; i < 4; i++) {                 // A: 128x32
            int idx = tid + i * 256;
            int row = idx >> 3, c4 = (idx & 7) * 4;
            cp16(base + (uint32_t)(row * KP + c4) * 4u,
                 g_q + (size_t)(m0 + row) * 256 + kc + c4, 16);
        }
        uint32_t bbase = base + (uint32_t)A_WORDS * 4u;
#pragma unroll
        for (int i = 0; i < 8; i++) {                 // B: 256x32
            int idx = tid + i * 256;
            int row = idx >> 3, c4 = (idx & 7) * 4;
            int nr = n0 + row;
            int ok = nr < NENT;
            cp16(bbase + (uint32_t)(row * KP + c4) * 4u,
                 rhs_w + (size_t)(ok ? nr : 0) * 256 + kc + c4, ok ? 16 : 0);
        }
    };

    float acc[4][8][4];
#pragma unroll
    for (int tm = 0; tm < 4; tm++)
#pragma unroll
        for (int tn = 0; tn < 8; tn++)
#pragma unroll
            for (int r = 0; r < 4; r++) acc[tm][tn][r] = 0.f;

    // prologue: stages 0,1
    issue_stage(0, 0);
    asm volatile("cp.async.commit_group;\n" ::: "memory");
    issue_stage(1, BK);
    asm volatile("cp.async.commit_group;\n" ::: "memory");

#pragma unroll 1
    for (int c = 0; c < RANK / BK; c++) {
        asm volatile("cp.async.wait_group 1;\n" ::: "memory");
        __syncthreads();

        // issue stage c+2 (overwrites buffer of chunk c-1; safe after the sync)
        if (c + 2 < RANK / BK) issue_stage((c + 2) % NST, (c + 2) * BK);
        asm volatile("cp.async.commit_group;\n" ::: "memory");

        const float* As = smem + (c % NST) * STG_WORDS;
        const uint32_t* Au = reinterpret_cast<const uint32_t*>(As);
        const uint32_t* Bu = reinterpret_cast<const uint32_t*>(As + A_WORDS);

#pragma unroll
        for (int kk = 0; kk < BK; kk += 8) {
            uint32_t af[4][4];
#pragma unroll
            for (int tm = 0; tm < 4; tm++) {
                int r = wm * 64 + tm * 16 + gid;
                af[tm][0] = Au[r * KP + kk + qid];
                af[tm][1] = Au[(r + 8) * KP + kk + qid];
                af[tm][2] = Au[r * KP + kk + qid + 4];
                af[tm][3] = Au[(r + 8) * KP + kk + qid + 4];
            }
#pragma unroll
            for (int tn = 0; tn < 8; tn++) {
                int nr = wn * 64 + tn * 8 + gid;
                uint32_t b0 = Bu[nr * KP + kk + qid];
                uint32_t b1 = Bu[nr * KP + kk + qid + 4];
#pragma unroll
                for (int tm = 0; tm < 4; tm++)
                    mma_tf32(acc[tm][tn], af[tm], b0, b1);
            }
        }
    }

    // epilogue: streaming stores (output never re-read; protect L2)
#pragma unroll
    for (int tm = 0; tm < 4; tm++) {
        int r = m0 + wm * 64 + tm * 16 + gid;
#pragma unroll
        for (int tn = 0; tn < 8; tn++) {
            int cb = n0 + wn * 64 + tn * 8 + 2 * qid;
            if (cb < NENT) {
                __stcs(reinterpret_cast<float2*>(out + (size_t)r * NENT + cb),
                       make_float2(acc[tm][tn][0], acc[tm][tn][1]));
                __stcs(reinterpret_cast<float2*>(out + (size_t)(r + 8) * NENT + cb),
                       make_float2(acc[tm][tn][2], acc[tm][tn][3]));
            }
        }
    }
}

// ---------------------------------------------------------------------------
extern "C" void kernel_launch(void* const* d_in, const int* in_sizes, int n_in,
                              void* d_out, int out_size) {
    const int*   x      = (const int*)d_in[0];
    const int*   nb     = (const int*)d_in[1];
    const float* lhs_w  = (const float*)d_in[2];
    const float* rel_w  = (const float*)d_in[3];
    const float* rhs_w  = (const float*)d_in[4];
    const float* W_w    = (const float*)d_in[5];
    const float* W_b    = (const float*)d_in[6];
    const float* W2_w   = (const float*)d_in[7];
    const float* W2_b   = (const float*)d_in[8];
    const float* Wo_w   = (const float*)d_in[9];
    const float* Wo_b   = (const float*)d_in[10];
    const float* Uo_w   = (const float*)d_in[11];
    const float* Uo_b   = (const float*)d_in[12];
    float* out = (float*)d_out;

    float* aux = nullptr;
    if (out_size >= 102400000 + 4 * 262144) aux = out + 102400000;

    static bool attr_set = false;
    if (!attr_set) {
        cudaFuncSetAttribute(gemm_tf32_kernel,
                             cudaFuncAttributeMaxDynamicSharedMemorySize, SMEM_BYTES);
        attr_set = true;
    }

    transpose_kernel<<<(512 * 256 + 256 * 256 + 255) / 256, 256>>>(W_w, W2_w);
    prep_kernel<<<B_SZ / 8, 256>>>(x, nb, lhs_w, rel_w, rhs_w,
                                   W_b, W2_b, Wo_w, Wo_b, Uo_w, Uo_b, aux);
    dim3 grid(B_SZ / BM, (NENT + BN - 1) / BN);
    gemm_tf32_kernel<<<grid, 256, SMEM_BYTES>>>(rhs_w, out);
}

// round 4
// speedup vs baseline: 1.3715x; 1.1505x over previous
#include <cuda_runtime.h>
#include <cuda_fp16.h>
#include <cstdint>
#include <math.h>

#define B_SZ   1024
#define RANK   256
#define NENT   100000
#define MAXNB  50

// GEMM tiling (fp16 mma.sync m16n8k16)
#define BM 128
#define BN 256
#define BK 32
#define KP 40                        // padded K stride in halves (80B rows)
#define NST 4
#define A_HALVES (BM * KP)           // 5120
#define B_HALVES (BN * KP)           // 10240
#define STG_BYTES ((A_HALVES + B_HALVES) * 2)   // 30720
#define SMEM_BYTES (NST * STG_BYTES)            // 122880

#define QSCALE 524288.0f             // 2^19
#define RSCALE 512.0f                // 2^9
#define OSCALE 3.725290298461914e-09f // 2^-28

// scratch (allocation-free rule: device globals)
__device__ __align__(16) __half g_q16[B_SZ * RANK];
__device__ __align__(16) __half g_rhs16[(size_t)NENT * RANK];
__device__ __align__(16) float g_Wt[512 * 256];
__device__ __align__(16) float g_W2t[256 * 256];

__device__ __forceinline__ void mma_f16(float* c, const uint32_t* a, uint32_t b0, uint32_t b1) {
    asm volatile(
        "mma.sync.aligned.m16n8k16.row.col.f32.f16.f16.f32 "
        "{%0,%1,%2,%3}, {%4,%5,%6,%7}, {%8,%9}, {%0,%1,%2,%3};\n"
        : "+f"(c[0]), "+f"(c[1]), "+f"(c[2]), "+f"(c[3])
        : "r"(a[0]), "r"(a[1]), "r"(a[2]), "r"(a[3]), "r"(b0), "r"(b1));
}
__device__ __forceinline__ void cp16(uint32_t saddr, const void* gptr, int sz) {
    asm volatile("cp.async.cg.shared.global [%0], [%1], 16, %2;\n"
                 :: "r"(saddr), "l"(gptr), "r"(sz));
}
#define CP_COMMIT() asm volatile("cp.async.commit_group;\n" ::: "memory")
#define CP_WAIT(n)  asm volatile("cp.async.wait_group %0;\n" :: "n"(n) : "memory")

// ---------------------------------------------------------------------------
// Kernel 0: transpose W_w and W2_w
// ---------------------------------------------------------------------------
__global__ void transpose_kernel(const float* __restrict__ W_w,
                                 const float* __restrict__ W2_w) {
    int idx = blockIdx.x * blockDim.x + threadIdx.x;
    if (idx < 512 * 256) {
        int i = idx >> 8, j = idx & 255;
        g_Wt[idx] = W_w[j * 512 + i];
    } else {
        int idx2 = idx - 512 * 256;
        if (idx2 < 256 * 256) {
            int k = idx2 >> 8, j = idx2 & 255;
            g_W2t[idx2] = W2_w[j * 256 + k];
        }
    }
}

// ---------------------------------------------------------------------------
// Kernel 0b: convert rhs_w (fp32) -> g_rhs16 (fp16, x RSCALE). 8 elems/thread.
// ---------------------------------------------------------------------------
__global__ __launch_bounds__(256) void convert_rhs_kernel(const float* __restrict__ rhs_w) {
    size_t i8 = ((size_t)blockIdx.x * blockDim.x + threadIdx.x) * 8;
    if (i8 >= (size_t)NENT * RANK) return;
    float4 v0 = *reinterpret_cast<const float4*>(rhs_w + i8);
    float4 v1 = *reinterpret_cast<const float4*>(rhs_w + i8 + 4);
    __half2 h[4];
    h[0] = __floats2half2_rn(v0.x * RSCALE, v0.y * RSCALE);
    h[1] = __floats2half2_rn(v0.z * RSCALE, v0.w * RSCALE);
    h[2] = __floats2half2_rn(v1.x * RSCALE, v1.y * RSCALE);
    h[3] = __floats2half2_rn(v1.z * RSCALE, v1.w * RSCALE);
    *reinterpret_cast<uint4*>(g_rhs16 + i8) = *reinterpret_cast<uint4*>(h);
}

// ---------------------------------------------------------------------------
// Kernel 1: prep — gathers, attention, gating (q -> scaled fp16)
// ---------------------------------------------------------------------------
__global__ __launch_bounds__(256) void prep_kernel(
    const int* __restrict__ x, const int* __restrict__ nb_idx,
    const float* __restrict__ lhs_w, const float* __restrict__ rel_w,
    const float* __restrict__ rhs_w,
    const float* __restrict__ W_b, const float* __restrict__ W2_b,
    const float* __restrict__ Wo_w, const float* __restrict__ Wo_b,
    const float* __restrict__ Uo_w, const float* __restrict__ Uo_b,
    float* __restrict__ aux)
{
    __shared__ float trp[8][512];
    __shared__ float w_sm[8][256];
    __shared__ float alpha[8][64];
    __shared__ float ctx_sm[8][256];
    __shared__ float red[8][8];
    __shared__ float g_sm[8];

    const int t = threadIdx.x;
    const int b0 = blockIdx.x * 8;
    const int lane = t & 31;
    const int warp = t >> 5;

    float lhsrel[8];
#pragma unroll
    for (int bb = 0; bb < 8; bb++) {
        int b = b0 + bb;
        int i0 = x[b * 3 + 0];
        int i1 = x[b * 3 + 1];
        int i2 = x[b * 3 + 2];
        float lv = lhs_w[(size_t)i0 * RANK + t];
        float rv = rel_w[(size_t)i1 * RANK + t];
        float hv = rhs_w[(size_t)i2 * RANK + t];
        trp[bb][t]       = lv;
        trp[bb][256 + t] = rv;
        lhsrel[bb] = lv * rv;
        if (aux) {
            aux[(size_t)b * RANK + t]              = lv;
            aux[262144 + (size_t)b * RANK + t]     = rv;
            aux[2 * 262144 + (size_t)b * RANK + t] = hv;
        }
    }
    __syncthreads();

    {
        float acc[8];
#pragma unroll
        for (int bb = 0; bb < 8; bb++) acc[bb] = 0.f;
        for (int i = 0; i < 512; i += 4) {
            float wv0 = g_Wt[(i + 0) * 256 + t];
            float wv1 = g_Wt[(i + 1) * 256 + t];
            float wv2 = g_Wt[(i + 2) * 256 + t];
            float wv3 = g_Wt[(i + 3) * 256 + t];
#pragma unroll
            for (int bb = 0; bb < 8; bb++) {
                const float4 tv = *reinterpret_cast<const float4*>(&trp[bb][i]);
                acc[bb] += wv0 * tv.x + wv1 * tv.y + wv2 * tv.z + wv3 * tv.w;
            }
        }
        float bias = W_b[t];
#pragma unroll
        for (int bb = 0; bb < 8; bb++) w_sm[bb][t] = acc[bb] + bias;
    }
    __syncthreads();

    {
        int bb = warp;
        int b = b0 + bb;
        for (int m = 0; m < MAXNB; m++) {
            int nb = __ldg(&nb_idx[b * MAXNB + m]);
            const float* r = rhs_w + (size_t)nb * RANK;
            float s = 0.f;
#pragma unroll
            for (int j = 0; j < 8; j++) {
                int k = lane + 32 * j;
                s += w_sm[bb][k] * __ldg(&r[k]);
            }
#pragma unroll
            for (int o = 16; o > 0; o >>= 1) s += __shfl_xor_sync(0xffffffffu, s, o);
            if (lane == 0) alpha[bb][m] = s;
        }
        __syncwarp();
        float v1 = (lane < MAXNB) ? alpha[bb][lane] : -1e30f;
        float v2 = (lane + 32 < MAXNB) ? alpha[bb][lane + 32] : -1e30f;
        float mx = fmaxf(v1, v2);
#pragma unroll
        for (int o = 16; o > 0; o >>= 1) mx = fmaxf(mx, __shfl_xor_sync(0xffffffffu, mx, o));
        float e1 = (lane < MAXNB) ? expf(v1 - mx) : 0.f;
        float e2 = (lane + 32 < MAXNB) ? expf(v2 - mx) : 0.f;
        float sm = e1 + e2;
#pragma unroll
        for (int o = 16; o > 0; o >>= 1) sm += __shfl_xor_sync(0xffffffffu, sm, o);
        float inv = 1.f / sm;
        if (lane < MAXNB) alpha[bb][lane] = e1 * inv;
        if (lane + 32 < MAXNB) alpha[bb][lane + 32] = e2 * inv;
    }
    __syncthreads();

#pragma unroll
    for (int bb = 0; bb < 8; bb++) {
        int base = (b0 + bb) * MAXNB;
        float acc = 0.f;
        for (int m = 0; m < MAXNB; m++) {
            int nb = __ldg(&nb_idx[base + m]);
            acc += alpha[bb][m] * __ldg(&rhs_w[(size_t)nb * RANK + t]);
        }
        ctx_sm[bb][t] = acc;
    }
    __syncthreads();

    float ec[8];
    {
        float acc[8];
#pragma unroll
        for (int bb = 0; bb < 8; bb++) acc[bb] = 0.f;
        for (int k = 0; k < 256; k += 4) {
            float w0 = g_W2t[(k + 0) * 256 + t];
            float w1 = g_W2t[(k + 1) * 256 + t];
            float w2 = g_W2t[(k + 2) * 256 + t];
            float w3 = g_W2t[(k + 3) * 256 + t];
#pragma unroll
            for (int bb = 0; bb < 8; bb++) {
                const float4 cv = *reinterpret_cast<const float4*>(&ctx_sm[bb][k]);
                acc[bb] += w0 * cv.x + w1 * cv.y + w2 * cv.z + w3 * cv.w;
            }
        }
        float bias = W2_b[t];
#pragma unroll
        for (int bb = 0; bb < 8; bb++) {
            ec[bb] = acc[bb] + bias;
            if (aux) aux[3 * 262144 + (size_t)(b0 + bb) * RANK + t] = ec[bb];
        }
    }

    {
        float uo = Uo_w[t], wo = Wo_w[t];
#pragma unroll
        for (int bb = 0; bb < 8; bb++) {
            float c = uo * lhsrel[bb] + wo * ec[bb];
#pragma unroll
            for (int o = 16; o > 0; o >>= 1) c += __shfl_xor_sync(0xffffffffu, c, o);
            if (lane == 0) red[bb][warp] = c;
        }
        __syncthreads();
        if (t < 8) {
            float s = 0.f;
#pragma unroll
            for (int w = 0; w < 8; w++) s += red[t][w];
            s += Uo_b[0] + Wo_b[0];
            g_sm[t] = 1.f / (1.f + expf(-s));
        }
        __syncthreads();
    }

    // q = lhs*rel*(g*e_c + 1 - g), scaled by 2^19, fp16
#pragma unroll
    for (int bb = 0; bb < 8; bb++) {
        float g = g_sm[bb];
        float q = lhsrel[bb] * (g * ec[bb] + 1.f - g);
        g_q16[(size_t)(b0 + bb) * RANK + t] = __float2half_rn(q * QSCALE);
    }
}

// ---------------------------------------------------------------------------
// Kernel 2: fp16 mma.sync GEMM: out = (q16 @ rhs16^T) * 2^-28.
// 128x256 tiles, BK=32 chunks, 4-stage cp.async pipeline, warp tile 64x64.
// ---------------------------------------------------------------------------
__global__ __launch_bounds__(256, 1) void gemm_f16_kernel(
    float* __restrict__ out)
{
    extern __shared__ __half smem[];

    const int tid = threadIdx.x;
    const int m0 = blockIdx.x * BM;
    const int n0 = blockIdx.y * BN;
    const int lane = tid & 31;
    const int warp = tid >> 5;
    const int wm = warp & 1;    // m offset 64*wm
    const int wn = warp >> 1;   // n offset 64*wn
    const int gid = lane >> 2;
    const int qid = lane & 3;

    const uint32_t smem_u32 = (uint32_t)__cvta_generic_to_shared(smem);

    auto issue_stage = [&](int buf, int kc) {
        uint32_t base = smem_u32 + (uint32_t)buf * STG_BYTES;
#pragma unroll
        for (int i = 0; i < 2; i++) {                 // A: 128 rows x 32 halves
            int idx = tid + i * 256;
            int row = idx >> 2, kq = idx & 3;
            cp16(base + (uint32_t)(row * (KP * 2) + kq * 16),
                 g_q16 + (size_t)(m0 + row) * RANK + kc + kq * 8, 16);
        }
        uint32_t bbase = base + (uint32_t)(A_HALVES * 2);
#pragma unroll
        for (int i = 0; i < 4; i++) {                 // B: 256 rows x 32 halves
            int idx = tid + i * 256;
            int row = idx >> 2, kq = idx & 3;
            int nr = n0 + row;
            int ok = nr < NENT;
            cp16(bbase + (uint32_t)(row * (KP * 2) + kq * 16),
                 g_rhs16 + (size_t)(ok ? nr : 0) * RANK + kc + kq * 8, ok ? 16 : 0);
        }
    };

    float acc[4][8][4];
#pragma unroll
    for (int tm = 0; tm < 4; tm++)
#pragma unroll
        for (int tn = 0; tn < 8; tn++)
#pragma unroll
            for (int r = 0; r < 4; r++) acc[tm][tn][r] = 0.f;

    issue_stage(0, 0);      CP_COMMIT();
    issue_stage(1, BK);     CP_COMMIT();
    issue_stage(2, 2 * BK); CP_COMMIT();

#pragma unroll 1
    for (int c = 0; c < RANK / BK; c++) {
        CP_WAIT(2);
        __syncthreads();

        if (c + 3 < RANK / BK) issue_stage((c + 3) & (NST - 1), (c + 3) * BK);
        CP_COMMIT();

        const uint32_t* S = reinterpret_cast<const uint32_t*>(
            smem + (size_t)(c & (NST - 1)) * (STG_BYTES / 2));
        const uint32_t* Au = S;                       // [row][KP/2 words]
        const uint32_t* Bu = S + A_HALVES / 2;

#pragma unroll
        for (int kk = 0; kk < BK / 16; kk++) {        // 2 k16 steps
            const int kw = kk * 8;                    // word offset (16 halves)
            uint32_t af[4][4];
#pragma unroll
            for (int tm = 0; tm < 4; tm++) {
                int r = wm * 64 + tm * 16 + gid;
                af[tm][0] = Au[r * (KP / 2) + kw + qid];
                af[tm][1] = Au[(r + 8) * (KP / 2) + kw + qid];
                af[tm][2] = Au[r * (KP / 2) + kw + qid + 4];
                af[tm][3] = Au[(r + 8) * (KP / 2) + kw + qid + 4];
            }
#pragma unroll
            for (int tn = 0; tn < 8; tn++) {
                int nr = wn * 64 + tn * 8 + gid;
                uint32_t b0 = Bu[nr * (KP / 2) + kw + qid];
                uint32_t b1 = Bu[nr * (KP / 2) + kw + qid + 4];
#pragma unroll
                for (int tm = 0; tm < 4; tm++)
                    mma_f16(acc[tm][tn], af[tm], b0, b1);
            }
        }
    }

    // epilogue: descale + streaming stores
#pragma unroll
    for (int tm = 0; tm < 4; tm++) {
        int r = m0 + wm * 64 + tm * 16 + gid;
#pragma unroll
        for (int tn = 0; tn < 8; tn++) {
            int cb = n0 + wn * 64 + tn * 8 + 2 * qid;
            if (cb < NENT) {
                __stcs(reinterpret_cast<float2*>(out + (size_t)r * NENT + cb),
                       make_float2(acc[tm][tn][0] * OSCALE, acc[tm][tn][1] * OSCALE));
                __stcs(reinterpret_cast<float2*>(out + (size_t)(r + 8) * NENT + cb),
                       make_float2(acc[tm][tn][2] * OSCALE, acc[tm][tn][3] * OSCALE));
            }
        }
    }
}

// ---------------------------------------------------------------------------
extern "C" void kernel_launch(void* const* d_in, const int* in_sizes, int n_in,
                              void* d_out, int out_size) {
    const int*   x      = (const int*)d_in[0];
    const int*   nb     = (const int*)d_in[1];
    const float* lhs_w  = (const float*)d_in[2];
    const float* rel_w  = (const float*)d_in[3];
    const float* rhs_w  = (const float*)d_in[4];
    const float* W_w    = (const float*)d_in[5];
    const float* W_b    = (const float*)d_in[6];
    const float* W2_w   = (const float*)d_in[7];
    const float* W2_b   = (const float*)d_in[8];
    const float* Wo_w   = (const float*)d_in[9];
    const float* Wo_b   = (const float*)d_in[10];
    const float* Uo_w   = (const float*)d_in[11];
    const float* Uo_b   = (const float*)d_in[12];
    float* out = (float*)d_out;

    float* aux = nullptr;
    if (out_size >= 102400000 + 4 * 262144) aux = out + 102400000;

    static bool attr_set = false;
    if (!attr_set) {
        cudaFuncSetAttribute(gemm_f16_kernel,
                             cudaFuncAttributeMaxDynamicSharedMemorySize, SMEM_BYTES);
        attr_set = true;
    }

    transpose_kernel<<<(512 * 256 + 256 * 256 + 255) / 256, 256>>>(W_w, W2_w);
    convert_rhs_kernel<<<(NENT * RANK / 8 + 255) / 256, 256>>>(rhs_w);
    prep_kernel<<<B_SZ / 8, 256>>>(x, nb, lhs_w, rel_w, rhs_w,
                                   W_b, W2_b, Wo_w, Wo_b, Uo_w, Uo_b, aux);
    dim3 grid(B_SZ / BM, (NENT + BN - 1) / BN);
    gemm_f16_kernel<<<grid, 256, SMEM_BYTES>>>(out);
}